// round 16
// baseline (speedup 1.0000x reference)
#include <cuda_runtime.h>
#include <cuda_bf16.h>
#include <cuda_fp16.h>
#include <cstdint>
#include <math.h>

// Problem constants
#define BATCH 2
#define SEQ 2048
#define DMODEL 1024
#define NHEADS 16
#define HDIM 64
#define N3 (3 * DMODEL)
#define ROWS (BATCH * SEQ)   // 4096

// Scratch (fp16 pipeline)
__device__ __half g_xh[(size_t)ROWS * DMODEL];
__device__ __half g_qkv[(size_t)ROWS * N3];
__device__ __half g_attnh[(size_t)ROWS * DMODEL];
__device__ __half g_wqkvT[(size_t)N3 * DMODEL];
__device__ __half g_woutT[(size_t)DMODEL * DMODEL];

// ===========================================================================
// Helpers
// ===========================================================================
__device__ __forceinline__ uint32_t smem_u32(const void* p) {
    uint32_t a;
    asm("{ .reg .u64 t; cvta.to.shared.u64 t, %1; cvt.u32.u64 %0, t; }"
        : "=r"(a) : "l"(p));
    return a;
}
__device__ __forceinline__ void cpasync16(uint32_t saddr, const void* gaddr) {
    asm volatile("cp.async.cg.shared.global [%0], [%1], 16;"
                 :: "r"(saddr), "l"(gaddr));
}
#define CP_COMMIT() asm volatile("cp.async.commit_group;" ::: "memory")
#define CP_WAIT2()  asm volatile("cp.async.wait_group 2;" ::: "memory")
#define CP_WAIT0()  asm volatile("cp.async.wait_group 0;" ::: "memory")

__device__ __forceinline__ void ldsm4(uint32_t* r, uint32_t addr) {
    asm volatile("ldmatrix.sync.aligned.m8n8.x4.shared.b16 {%0,%1,%2,%3}, [%4];"
                 : "=r"(r[0]), "=r"(r[1]), "=r"(r[2]), "=r"(r[3]) : "r"(addr));
}
__device__ __forceinline__ void ldsm4t(uint32_t* r, uint32_t addr) {
    asm volatile("ldmatrix.sync.aligned.m8n8.x4.trans.shared.b16 {%0,%1,%2,%3}, [%4];"
                 : "=r"(r[0]), "=r"(r[1]), "=r"(r[2]), "=r"(r[3]) : "r"(addr));
}
__device__ __forceinline__ void mma16816h(float* c, const uint32_t* a, const uint32_t* b) {
    asm volatile(
        "mma.sync.aligned.m16n8k16.row.col.f32.f16.f16.f32 "
        "{%0,%1,%2,%3}, {%4,%5,%6,%7}, {%8,%9}, {%0,%1,%2,%3};"
        : "+f"(c[0]), "+f"(c[1]), "+f"(c[2]), "+f"(c[3])
        : "r"(a[0]), "r"(a[1]), "r"(a[2]), "r"(a[3]), "r"(b[0]), "r"(b[1]));
}
__device__ __forceinline__ uint32_t pack_h2(float a, float b) {
    __half2 h = __floats2half2_rn(a, b);
    return *(uint32_t*)&h;
}

// ===========================================================================
// Convert kernels
// ===========================================================================
__global__ void conv_h(const float* __restrict__ in, __half* __restrict__ out) {
    int vi = blockIdx.x * blockDim.x + threadIdx.x;
    float4 v = *(const float4*)(in + (size_t)vi * 4);
    __half2 h0 = __floats2half2_rn(v.x, v.y);
    __half2 h1 = __floats2half2_rn(v.z, v.w);
    uint2 u = make_uint2(*(uint32_t*)&h0, *(uint32_t*)&h1);
    *(uint2*)(out + (size_t)vi * 4) = u;
}

__global__ void transp_h(const float* __restrict__ W, __half* __restrict__ Bt,
                         int K, int N) {
    __shared__ float t[32][33];
    int n0 = blockIdx.x * 32, k0 = blockIdx.y * 32;
    int tx = threadIdx.x, ty = threadIdx.y;   // block (32, 8)
#pragma unroll
    for (int i = 0; i < 4; i++)
        t[ty + 8 * i][tx] = W[(size_t)(k0 + ty + 8 * i) * N + n0 + tx];
    __syncthreads();
#pragma unroll
    for (int i = 0; i < 4; i++) {
        int n = n0 + ty + 8 * i;
        int k = k0 + tx;
        Bt[(size_t)n * K + k] = __float2half(t[tx][ty + 8 * i]);
    }
}

// ===========================================================================
// Warp-MMA GEMM: C[m][n] = sum_k A[m][k] * Bt[n][k]  (fp16 in, fp32/fp16 out)
// CTA tile 128x128, K-stage 32, 256 threads, 4-stage cp.async pipeline,
// 2 CTAs/SM. Per iteration: barrier -> cp.async issue -> ALL ldmatrix frags
// (both k16 steps) -> 32 MMAs. One barrier per iteration.
// ===========================================================================
#define GK 32
#define AROW 40
#define ATILE_B (128 * AROW * 2)
#define STAGE_B (2 * ATILE_B)
#define NSTAGE 4
#define GEMM_SMEM (NSTAGE * STAGE_B)

template <bool HALFOUT>
__global__ __launch_bounds__(256, 2)
void gemm_mma(const __half* __restrict__ A, const __half* __restrict__ Bt,
              void* __restrict__ Cv, int Nc, int KK) {
    extern __shared__ __align__(128) char smbuf[];
    const uint32_t sbase = smem_u32(smbuf);

    const int tid  = threadIdx.x;
    const int wid  = tid >> 5;
    const int lane = tid & 31;
    const int m0 = blockIdx.y * 128;
    const int n0 = blockIdx.x * 128;
    const int wm = wid & 3;
    const int wn = wid >> 2;

    float acc[2][8][4];
#pragma unroll
    for (int i = 0; i < 2; i++)
#pragma unroll
        for (int j = 0; j < 8; j++)
#pragma unroll
            for (int l = 0; l < 4; l++) acc[i][j][l] = 0.f;

    const int lrow = tid >> 1;
    const int lc   = (tid & 1) * 2;
    const int niter = KK / GK;

#define SM_A(st) (sbase + (st) * STAGE_B)
#define SM_B(st) (sbase + (st) * STAGE_B + ATILE_B)
#define LOAD_STAGE(st, it) do {                                               \
    const __half* ga = A + (size_t)(m0 + lrow) * KK + (size_t)(it) * GK + lc * 8; \
    const __half* gb = Bt + (size_t)(n0 + lrow) * KK + (size_t)(it) * GK + lc * 8; \
    uint32_t sa = SM_A(st) + lrow * (AROW * 2) + lc * 16;                     \
    uint32_t sb = SM_B(st) + lrow * (AROW * 2) + lc * 16;                     \
    cpasync16(sa, ga); cpasync16(sa + 16, ga + 8);                            \
    cpasync16(sb, gb); cpasync16(sb + 16, gb + 8);                            \
    CP_COMMIT();                                                              \
} while (0)

    LOAD_STAGE(0, 0);
    LOAD_STAGE(1, 1);
    LOAD_STAGE(2, 2);

    const int a_r16 = lane & 15;
    const int a_hi  = (lane & 16) ? 16 : 0;
    const int b_r   = (lane & 7) + ((lane & 16) ? 8 : 0);
    const int b_hi  = (lane & 8) ? 16 : 0;

    for (int it = 0; it < niter; it++) {
        const int st = it & (NSTAGE - 1);
        CP_WAIT2();
        __syncthreads();   // stage `st` visible; stage (it+3)&3 free for reload

        // Issue next stage's gmem loads FIRST — maximal overlap with compute
        if (it + 3 < niter) LOAD_STAGE((it + 3) & (NSTAGE - 1), it + 3);
        else CP_COMMIT();

        const uint32_t ab = SM_A(st);
        const uint32_t bb = SM_B(st);

        // Load ALL frags for both k16 steps, then do all 32 MMAs.
        uint32_t a0[2][4], a1[2][4], bfr[2][8][2];
#pragma unroll
        for (int s = 0; s < 2; s++) {
            ldsm4(a0[s], ab + (wm * 32 + a_r16) * (AROW * 2) + s * 32 + a_hi);
            ldsm4(a1[s], ab + (wm * 32 + 16 + a_r16) * (AROW * 2) + s * 32 + a_hi);
#pragma unroll
            for (int g = 0; g < 4; g++) {
                uint32_t r[4];
                ldsm4(r, bb + (wn * 64 + g * 16 + b_r) * (AROW * 2) + s * 32 + b_hi);
                bfr[s][2 * g][0] = r[0]; bfr[s][2 * g][1] = r[1];
                bfr[s][2 * g + 1][0] = r[2]; bfr[s][2 * g + 1][1] = r[3];
            }
        }
#pragma unroll
        for (int s = 0; s < 2; s++) {
#pragma unroll
            for (int nt = 0; nt < 8; nt++) {
                mma16816h(acc[0][nt], a0[s], bfr[s][nt]);
                mma16816h(acc[1][nt], a1[s], bfr[s][nt]);
            }
        }
    }

    const int g4 = lane >> 2;
    const int q4 = lane & 3;
#pragma unroll
    for (int mt = 0; mt < 2; mt++) {
        int r0 = m0 + wm * 32 + mt * 16 + g4;
#pragma unroll
        for (int nt = 0; nt < 8; nt++) {
            int cc = n0 + wn * 64 + nt * 8 + q4 * 2;
            if (HALFOUT) {
                __half* Cb = (__half*)Cv;
                *(uint32_t*)(Cb + (size_t)r0 * Nc + cc) =
                    pack_h2(acc[mt][nt][0], acc[mt][nt][1]);
                *(uint32_t*)(Cb + (size_t)(r0 + 8) * Nc + cc) =
                    pack_h2(acc[mt][nt][2], acc[mt][nt][3]);
            } else {
                float* Cf = (float*)Cv;
                *(float2*)(Cf + (size_t)r0 * Nc + cc) =
                    make_float2(acc[mt][nt][0], acc[mt][nt][1]);
                *(float2*)(Cf + (size_t)(r0 + 8) * Nc + cc) =
                    make_float2(acc[mt][nt][2], acc[mt][nt][3]);
            }
        }
    }
#undef LOAD_STAGE
#undef SM_A
#undef SM_B
}

// ===========================================================================
// FA2 flash attention (causal), fp16 MMA + fp32 softmax, fp16 out.
// Q-tile 128 rows per CTA, 256 threads = 8 warps (16 q-rows each, full 64-key
// width). K-tile 64. Register softmax stats; P in registers; K/V double-buffer.
// Grid (SEQ/128, NHEADS, BATCH).
// ===========================================================================
#define FA_ASTR 72                        // halves per smem row (144 B)
#define FA_KTILE (64 * FA_ASTR * 2)       // 9216 B (K or V tile)
#define FA_QTILE (128 * FA_ASTR * 2)      // 18432 B
#define FA_Q   0
#define FA_KV  FA_QTILE                   // K0,V0,K1,V1
#define FA_SMEM (FA_KV + 4 * FA_KTILE)    // 55296 B

__global__ __launch_bounds__(256)
void attn_mma(const __half* __restrict__ qkv, __half* __restrict__ out) {
    extern __shared__ __align__(128) char sm[];
    const uint32_t sb = smem_u32(sm);

    const int tid  = threadIdx.x;
    const int wid  = tid >> 5;          // 0..7: q-slice of 16 rows
    const int lane = tid & 31;
    const int g4 = lane >> 2;
    const int q4 = lane & 3;
    const int qb = gridDim.x - 1 - blockIdx.x;   // longest blocks first
    const int h  = blockIdx.y;
    const int b  = blockIdx.z;
    const int q0 = qb * 128;
    const int ntiles = 2 * qb + 2;

    const __half* base = qkv + (size_t)b * SEQ * N3;
    const __half* qp = base + (size_t)q0 * N3 + h * HDIM;

    const int a_r16 = lane & 15;
    const int a_hi  = (lane & 16) ? 16 : 0;
    const int b_r   = (lane & 7) + ((lane & 16) ? 8 : 0);
    const int b_hi  = (lane & 8) ? 16 : 0;
    const int v_r   = (lane & 7) + ((lane & 8) ? 8 : 0);
    const int v_c   = (lane & 16) ? 8 : 0;

    // Prefetch K/V tile 0 (cp.async: 512 x 16B each over 256 threads)
    {
        const __half* kp = base + DMODEL + h * HDIM;
        const __half* vp = base + 2 * DMODEL + h * HDIM;
#pragma unroll
        for (int l = 0; l < 2; l++) {
            int idx = tid + l * 256;          // 0..511
            int row = idx >> 3;               // 0..63
            int dc  = (idx & 7) * 8;
            cpasync16(sb + FA_KV + row * (FA_ASTR * 2) + dc * 2,
                      kp + (size_t)row * N3 + dc);
            cpasync16(sb + FA_KV + FA_KTILE + row * (FA_ASTR * 2) + dc * 2,
                      vp + (size_t)row * N3 + dc);
        }
        CP_COMMIT();
        // Q tile: 128 rows x 64 halves (plain vector loads)
#pragma unroll
        for (int l = 0; l < 4; l++) {
            int idx = tid + l * 256;          // 0..1023
            int row = idx >> 3;               // 0..127
            int dc  = (idx & 7) * 8;
            uint4 v = *(const uint4*)(qp + (size_t)row * N3 + dc);
            *(uint4*)(sm + FA_Q + row * (FA_ASTR * 2) + dc * 2) = v;
        }
        CP_WAIT0();
    }
    __syncthreads();

    // Q A-frags in registers for whole kernel
    uint32_t qf[4][4];
#pragma unroll
    for (int s = 0; s < 4; s++)
        ldsm4(qf[s], sb + FA_Q + (wid * 16 + a_r16) * (FA_ASTR * 2) + s * 32 + a_hi);

    float O[8][4];
#pragma unroll
    for (int nt = 0; nt < 8; nt++)
#pragma unroll
        for (int j = 0; j < 4; j++) O[nt][j] = 0.f;

    float m1 = -1e30f, m2 = -1e30f, l1 = 0.f, l2 = 0.f;
    const int row1 = wid * 16 + g4;      // local q row (0..127)
    const int row2 = row1 + 8;

    for (int jt = 0; jt < ntiles; jt++) {
        const int buf = jt & 1;
        const uint32_t kb = sb + FA_KV + buf * 2 * FA_KTILE;
        const uint32_t vb = kb + FA_KTILE;

        // Prefetch next K/V tile
        if (jt + 1 < ntiles) {
            const int nbuf = buf ^ 1;
            const __half* kp = base + (size_t)(jt + 1) * 64 * N3 + DMODEL + h * HDIM;
            const __half* vp = base + (size_t)(jt + 1) * 64 * N3 + 2 * DMODEL + h * HDIM;
#pragma unroll
            for (int l = 0; l < 2; l++) {
                int idx = tid + l * 256;
                int row = idx >> 3;
                int dc  = (idx & 7) * 8;
                cpasync16(sb + FA_KV + nbuf * 2 * FA_KTILE + row * (FA_ASTR * 2) + dc * 2,
                          kp + (size_t)row * N3 + dc);
                cpasync16(sb + FA_KV + nbuf * 2 * FA_KTILE + FA_KTILE +
                              row * (FA_ASTR * 2) + dc * 2,
                          vp + (size_t)row * N3 + dc);
            }
            CP_COMMIT();
        }

        // ---- S = Q @ K^T : 16 q-rows x 64 keys ----
        float sa[8][4];
#pragma unroll
        for (int nt = 0; nt < 8; nt++)
#pragma unroll
            for (int j = 0; j < 4; j++) sa[nt][j] = 0.f;

#pragma unroll
        for (int s = 0; s < 4; s++) {
            uint32_t bf[8][2];
#pragma unroll
            for (int g = 0; g < 4; g++) {
                uint32_t r[4];
                ldsm4(r, kb + (g * 16 + b_r) * (FA_ASTR * 2) + s * 32 + b_hi);
                bf[2 * g][0] = r[0]; bf[2 * g][1] = r[1];
                bf[2 * g + 1][0] = r[2]; bf[2 * g + 1][1] = r[3];
            }
#pragma unroll
            for (int nt = 0; nt < 8; nt++)
                mma16816h(sa[nt], qf[s], bf[nt]);
        }

        // Scale + causal mask (diag tiles: jt >= 2*qb; kq = k0 - q0)
        const bool diag = (jt >= 2 * qb);
        const int kq = jt * 64 - q0;
#pragma unroll
        for (int nt = 0; nt < 8; nt++) {
            sa[nt][0] *= 0.125f; sa[nt][1] *= 0.125f;
            sa[nt][2] *= 0.125f; sa[nt][3] *= 0.125f;
            if (diag) {
                int c = kq + nt * 8 + q4 * 2;
                if (c > row1)     sa[nt][0] = -1e30f;
                if (c + 1 > row1) sa[nt][1] = -1e30f;
                if (c > row2)     sa[nt][2] = -1e30f;
                if (c + 1 > row2) sa[nt][3] = -1e30f;
            }
        }

        // Row max via quad shuffles
        float mx1 = -1e30f, mx2 = -1e30f;
#pragma unroll
        for (int nt = 0; nt < 8; nt++) {
            mx1 = fmaxf(mx1, fmaxf(sa[nt][0], sa[nt][1]));
            mx2 = fmaxf(mx2, fmaxf(sa[nt][2], sa[nt][3]));
        }
        mx1 = fmaxf(mx1, __shfl_xor_sync(0xffffffffu, mx1, 1));
        mx1 = fmaxf(mx1, __shfl_xor_sync(0xffffffffu, mx1, 2));
        mx2 = fmaxf(mx2, __shfl_xor_sync(0xffffffffu, mx2, 1));
        mx2 = fmaxf(mx2, __shfl_xor_sync(0xffffffffu, mx2, 2));

        const float mn1 = fmaxf(m1, mx1);
        const float mn2 = fmaxf(m2, mx2);
        const float al1 = __expf(m1 - mn1);
        const float al2 = __expf(m2 - mn2);
        m1 = mn1; m2 = mn2;

        // exp; build P A-frags in registers; row sums
        uint32_t ph[4][4];
        float s1 = 0.f, s2 = 0.f;
#pragma unroll
        for (int s = 0; s < 4; s++) {
            float p00 = __expf(sa[2 * s][0] - m1);
            float p01 = __expf(sa[2 * s][1] - m1);
            float p02 = __expf(sa[2 * s][2] - m2);
            float p03 = __expf(sa[2 * s][3] - m2);
            float p10 = __expf(sa[2 * s + 1][0] - m1);
            float p11 = __expf(sa[2 * s + 1][1] - m1);
            float p12 = __expf(sa[2 * s + 1][2] - m2);
            float p13 = __expf(sa[2 * s + 1][3] - m2);
            s1 += p00 + p01 + p10 + p11;
            s2 += p02 + p03 + p12 + p13;
            ph[s][0] = pack_h2(p00, p01);
            ph[s][1] = pack_h2(p02, p03);
            ph[s][2] = pack_h2(p10, p11);
            ph[s][3] = pack_h2(p12, p13);
        }
        s1 += __shfl_xor_sync(0xffffffffu, s1, 1);
        s1 += __shfl_xor_sync(0xffffffffu, s1, 2);
        s2 += __shfl_xor_sync(0xffffffffu, s2, 1);
        s2 += __shfl_xor_sync(0xffffffffu, s2, 2);
        l1 = l1 * al1 + s1;
        l2 = l2 * al2 + s2;

#pragma unroll
        for (int nt = 0; nt < 8; nt++) {
            O[nt][0] *= al1; O[nt][1] *= al1;
            O[nt][2] *= al2; O[nt][3] *= al2;
        }

        // ---- O += P @ V ----
#pragma unroll
        for (int s = 0; s < 4; s++) {
            uint32_t bf[8][2];
#pragma unroll
            for (int g = 0; g < 4; g++) {
                uint32_t r[4];
                ldsm4t(r, vb + (s * 16 + v_r) * (FA_ASTR * 2) + (g * 16 + v_c) * 2);
                bf[2 * g][0] = r[0]; bf[2 * g][1] = r[1];
                bf[2 * g + 1][0] = r[2]; bf[2 * g + 1][1] = r[3];
            }
#pragma unroll
            for (int nt = 0; nt < 8; nt++)
                mma16816h(O[nt], ph[s], bf[nt]);
        }

        CP_WAIT0();        // prefetch landed
        __syncthreads();   // all warps done with old buffer
    }

    // Finalize -> fp16 out
    const float li1 = 1.f / l1;
    const float li2 = 1.f / l2;
    __half* op = out + ((size_t)b * SEQ + q0) * DMODEL + h * HDIM;
#pragma unroll
    for (int nt = 0; nt < 8; nt++) {
        int c = nt * 8 + q4 * 2;
        *(uint32_t*)(op + (size_t)row1 * DMODEL + c) =
            pack_h2(O[nt][0] * li1, O[nt][1] * li1);
        *(uint32_t*)(op + (size_t)row2 * DMODEL + c) =
            pack_h2(O[nt][2] * li2, O[nt][3] * li2);
    }
}

// ===========================================================================
// Launch
// ===========================================================================
extern "C" void kernel_launch(void* const* d_in, const int* in_sizes, int n_in,
                              void* d_out, int out_size) {
    const float* x    = (const float*)d_in[0];
    // d_in[1] = mask (tril) — causality applied analytically
    const float* Wqkv = (const float*)d_in[2];
    const float* Wout = (const float*)d_in[3];
    float* out = (float*)d_out;

    __half *xh, *qkv, *attnh, *wqkvT, *woutT;
    cudaGetSymbolAddress((void**)&xh, g_xh);
    cudaGetSymbolAddress((void**)&qkv, g_qkv);
    cudaGetSymbolAddress((void**)&attnh, g_attnh);
    cudaGetSymbolAddress((void**)&wqkvT, g_wqkvT);
    cudaGetSymbolAddress((void**)&woutT, g_woutT);

    cudaFuncSetAttribute(gemm_mma<true>, cudaFuncAttributeMaxDynamicSharedMemorySize,
                         GEMM_SMEM);
    cudaFuncSetAttribute(gemm_mma<false>, cudaFuncAttributeMaxDynamicSharedMemorySize,
                         GEMM_SMEM);
    cudaFuncSetAttribute(attn_mma, cudaFuncAttributeMaxDynamicSharedMemorySize,
                         FA_SMEM);

    // 1. Convert inputs to fp16
    conv_h<<<(ROWS * DMODEL / 4) / 256, 256>>>(x, xh);
    transp_h<<<dim3(N3 / 32, DMODEL / 32), dim3(32, 8)>>>(Wqkv, wqkvT, DMODEL, N3);
    transp_h<<<dim3(DMODEL / 32, DMODEL / 32), dim3(32, 8)>>>(Wout, woutT, DMODEL, DMODEL);

    // 2. QKV projection (fp16 HMMA), fp16 out
    gemm_mma<true><<<dim3(N3 / 128, ROWS / 128), 256, GEMM_SMEM>>>(xh, wqkvT, qkv,
                                                                   N3, DMODEL);

    // 3. Causal flash attention (fp16 tensor cores, 128-row q-tiles), fp16 out
    attn_mma<<<dim3(SEQ / 128, NHEADS, BATCH), 256, FA_SMEM>>>(qkv, attnh);

    // 4. Output projection (fp16 HMMA), fp32 out
    gemm_mma<false><<<dim3(DMODEL / 128, ROWS / 128), 256, GEMM_SMEM>>>(attnh, woutT, out,
                                                                        DMODEL, DMODEL);
}